// round 5
// baseline (speedup 1.0000x reference)
#include <cuda_runtime.h>

typedef unsigned long long u64;
typedef unsigned int u32;

#define N_BATCH 64
#define C_ALL 256
#define HW 1024
#define EDGES 10
#define STATE_ELEMS (N_BATCH * C_ALL * HW)   // 16,777,216 floats = 64 MB

// Scratch: states 1..3 (state 0 = input x, state 4 = d_out)
__device__ float g_state[3][STATE_ELEMS];
// Combined 9x9 weights, layout [e][ci][tap(81)][o(64)], 16B-aligned for float4
__device__ __align__(16) float g_W9[EDGES * 64 * 81 * 64];
__device__ float g_wsoft[EDGES][12];

__device__ __forceinline__ void ffma2(u64 &d, u64 a, u64 b) {
    asm("fma.rn.f32x2 %0, %1, %2, %0;" : "+l"(d) : "l"(a), "l"(b));
}
__device__ __forceinline__ u64 dup2(float v) {
    u64 d; u32 r = __float_as_uint(v);
    asm("mov.b64 %0, {%1, %1};" : "=l"(d) : "r"(r));
    return d;
}
__device__ __forceinline__ u64 pack2(float a, float b) {
    u64 d; u32 ra = __float_as_uint(a), rb = __float_as_uint(b);
    asm("mov.b64 %0, {%1, %2};" : "=l"(d) : "r"(ra), "r"(rb));
    return d;
}
__device__ __forceinline__ void unpack2(u64 d, float &a, float &b) {
    u32 ra, rb;
    asm("mov.b64 {%0, %1}, %2;" : "=r"(ra), "=r"(rb) : "l"(d));
    a = __uint_as_float(ra); b = __uint_as_float(rb);
}

// ---------------------------------------------------------------------------
// 1) Per-edge softmax of arch params
// ---------------------------------------------------------------------------
__global__ void softmax_kernel(const float* __restrict__ arch,
                               const float* __restrict__ norms) {
    int e = threadIdx.x;
    if (e >= EDGES) return;
    int node = 0, base = 0;
    while (base + node + 1 <= e) { base += node + 1; node++; }
    int i = e - base;
    const float* a = arch + (node * 5 + i) * 12;
    float norm = fmaxf(norms[node * 5 + i], 1e-5f);
    float inv = 1.0f / norm;   // STRENGTH = 1.0
    float t[12];
    float m = -3.4e38f;
    for (int j = 0; j < 12; j++) { t[j] = a[j] * inv; m = fmaxf(m, t[j]); }
    float s = 0.f;
    for (int j = 0; j < 12; j++) { t[j] = expf(t[j] - m); s += t[j]; }
    float invs = 1.0f / s;
    for (int j = 0; j < 12; j++) g_wsoft[e][j] = t[j] * invs;
}

// ---------------------------------------------------------------------------
// 2) Fold all 8 conv ops (+identity) of an edge into one 9x9 dense kernel.
// ---------------------------------------------------------------------------
__global__ void build_w9_kernel(
    const float* __restrict__ w3, const float* __restrict__ w5,
    const float* __restrict__ w7, const float* __restrict__ w1,
    const float* __restrict__ s3dw, const float* __restrict__ s3pw,
    const float* __restrict__ s5dw, const float* __restrict__ s5pw,
    const float* __restrict__ d3, const float* __restrict__ d5)
{
    int e = blockIdx.x, ci = blockIdx.y, o = threadIdx.x;
    float wid = g_wsoft[e][0];
    float a3  = g_wsoft[e][1];
    float a5  = g_wsoft[e][2];
    float a7  = g_wsoft[e][3];
    float a1  = g_wsoft[e][4];
    float as3 = g_wsoft[e][7];
    float as5 = g_wsoft[e][8];
    float ad3 = g_wsoft[e][9];
    float ad5 = g_wsoft[e][10];

    int eoc = (e * 64 + o) * 64 + ci;   // OIHW-style [e][o][ci]
    int eci = e * 64 + ci;              // depthwise  [e][ci]
    float pw3 = s3pw[eoc];
    float pw5 = s5pw[eoc];
    float w1v = w1[eoc];

    float* outp = g_W9 + ((e * 64 + ci) * 81) * 64 + o;

    for (int tap = 0; tap < 81; tap++) {
        int dy = tap / 9, dx = tap % 9;
        float v = 0.f;
        if (dy >= 3 && dy <= 5 && dx >= 3 && dx <= 5) {
            int k = (dy - 3) * 3 + (dx - 3);
            v += a3  * w3[eoc * 9 + k];
            v += as3 * pw3 * s3dw[eci * 9 + k];
        }
        if (dy >= 2 && dy <= 6 && dx >= 2 && dx <= 6) {
            int k = (dy - 2) * 5 + (dx - 2);
            v += a5  * w5[eoc * 25 + k];
            v += as5 * pw5 * s5dw[eci * 25 + k];
            if (!((dy - 2) & 1) && !((dx - 2) & 1))
                v += ad3 * d3[eoc * 9 + ((dy - 2) >> 1) * 3 + ((dx - 2) >> 1)];
        }
        if (dy >= 1 && dy <= 7 && dx >= 1 && dx <= 7)
            v += a7 * w7[eoc * 49 + (dy - 1) * 7 + (dx - 1)];
        if (!(dy & 1) && !(dx & 1))
            v += ad5 * d5[eoc * 25 + (dy >> 1) * 5 + (dx >> 1)];
        if (dy == 4 && dx == 4) {
            v += a1 * w1v;
            if (o == ci) v += wid;
        }
        outp[tap * 64] = v;
    }
}

// ---------------------------------------------------------------------------
// 3) Per-node pooling accumulation (writes the node's acc buffer)
// ---------------------------------------------------------------------------
__global__ void __launch_bounds__(256) pool_kernel(
    const float* __restrict__ x, float* __restrict__ out, int node)
{
    __shared__ float pl[1024];
    int c = blockIdx.x, n = blockIdx.y, tid = threadIdx.x;
    float acc[4] = {0.f, 0.f, 0.f, 0.f};
    int ebase = node * (node + 1) / 2;

    for (int i = 0; i <= node; i++) {
        const float* s = (i == 0) ? x : g_state[i - 1];
        const float* p = s + ((size_t)n * C_ALL + c) * HW;
        __syncthreads();
        for (int t = tid; t < 1024; t += 256) pl[t] = p[t];
        __syncthreads();
        float w5 = g_wsoft[ebase + i][5];
        float w6 = g_wsoft[ebase + i][6];
        #pragma unroll
        for (int k = 0; k < 4; k++) {
            int pix = tid + 256 * k;
            int y = pix >> 5, xx = pix & 31;
            float m = -3.4e38f, sum = 0.f;
            #pragma unroll
            for (int dy = -1; dy <= 1; dy++) {
                int yy = y + dy;
                if (yy < 0 || yy > 31) continue;
                #pragma unroll
                for (int dx = -1; dx <= 1; dx++) {
                    int xc = xx + dx;
                    if (xc < 0 || xc > 31) continue;
                    float v = pl[yy * 32 + xc];
                    m = fmaxf(m, v);
                    sum += v;
                }
            }
            acc[k] += w5 * m + w6 * (sum * (1.f / 9.f));
        }
    }

    float* dst = (node == 3) ? out : g_state[node];
    float* dp = dst + ((size_t)n * C_ALL + c) * HW;
    #pragma unroll
    for (int k = 0; k < 4; k++) dp[tid + 256 * k] = acc[k];
}

// ---------------------------------------------------------------------------
// 4) Fused 9x9 conv, register-sliding-window f32x2 version.
//    Block (256 thr): one image n, 8 output channels, full 32x32.
//    Thread: 8 adjacent x-pixels (one row) x 4 output channels (2 o-pairs).
//    Per (ci,dy): 4x LDS.128 input (conflict-free, row stride 44), 16 ALU
//    dup-packs, 18 broadcast LDS.64 weights, 144 FFMA2 -> FMA-pipe bound.
// ---------------------------------------------------------------------------
#define PLANE_STRIDE 44
#define PLANE_FLOATS (40 * PLANE_STRIDE)

__global__ void __launch_bounds__(256, 2) conv9_kernel(
    const float* __restrict__ x, float* __restrict__ out,
    int srcsel, int dstsel, const int* __restrict__ idxrow, int e)
{
    __shared__ float plane[PLANE_FLOATS];   // 40 rows x 44 stride (cols 0..39 used)
    __shared__ u64 wsm[81 * 4];             // [tap][pair0..3] (8 channels as 4 o-pairs)
    __shared__ int ids[64];

    const float* src = (srcsel == 0) ? x : g_state[srcsel - 1];
    float* dst = (dstsel == 4) ? out : g_state[dstsel - 1];
    const float* W = g_W9 + (size_t)e * (64 * 81 * 64);

    int tid = threadIdx.x;
    int n = blockIdx.x;
    int o0 = blockIdx.y * 8;

    if (tid < 64) ids[tid] = idxrow[tid];
    // Zero entire padded plane once; interior overwritten per ci, halo stays 0.
    for (int t = tid; t < PLANE_FLOATS; t += 256) plane[t] = 0.f;
    __syncthreads();

    int cg = tid >> 7;          // channel group: 0 -> pairs 0,1 ; 1 -> pairs 2,3
    int r  = tid & 127;
    int y  = r >> 2;            // 0..31 output row
    int xg = r & 3;             // x-group
    int x0 = xg * 8;            // output cols x0..x0+7

    u64 acc[2][8];
    #pragma unroll
    for (int p = 0; p < 2; p++)
        #pragma unroll
        for (int px = 0; px < 8; px++) acc[p][px] = 0ull;

    const float* srcn = src + (size_t)n * (C_ALL * HW);

    for (int ci = 0; ci < 64; ci++) {
        __syncthreads();   // previous iteration's consumers done
        // interior load: 1024 coalesced floats into padded plane
        const float* pg = srcn + (size_t)ids[ci] * HW;
        #pragma unroll
        for (int k = 0; k < 4; k++) {
            int t = tid + 256 * k;
            plane[(4 + (t >> 5)) * PLANE_STRIDE + 4 + (t & 31)] = pg[t];
        }
        // weights: 81 taps x 8 channels -> 324 o-pair u64s
        const float* Wci = W + (ci * 81) * 64 + o0;
        if (tid < 162) {
            int tap = tid >> 1, h = tid & 1;
            float4 w4 = *reinterpret_cast<const float4*>(Wci + tap * 64 + h * 4);
            wsm[tap * 4 + h * 2]     = pack2(w4.x, w4.y);
            wsm[tap * 4 + h * 2 + 1] = pack2(w4.z, w4.w);
        }
        __syncthreads();

        const u64* wrow = wsm + cg * 2;
        for (int dy = 0; dy < 9; dy++) {
            const float* rp = plane + (y + dy) * PLANE_STRIDE + x0;
            float4 f0 = *reinterpret_cast<const float4*>(rp);
            float4 f1 = *reinterpret_cast<const float4*>(rp + 4);
            float4 f2 = *reinterpret_cast<const float4*>(rp + 8);
            float4 f3 = *reinterpret_cast<const float4*>(rp + 12);
            u64 d[16];
            d[0]  = dup2(f0.x); d[1]  = dup2(f0.y); d[2]  = dup2(f0.z); d[3]  = dup2(f0.w);
            d[4]  = dup2(f1.x); d[5]  = dup2(f1.y); d[6]  = dup2(f1.z); d[7]  = dup2(f1.w);
            d[8]  = dup2(f2.x); d[9]  = dup2(f2.y); d[10] = dup2(f2.z); d[11] = dup2(f2.w);
            d[12] = dup2(f3.x); d[13] = dup2(f3.y); d[14] = dup2(f3.z); d[15] = dup2(f3.w);
            #pragma unroll
            for (int dx = 0; dx < 9; dx++) {
                u64 w0 = wrow[(dy * 9 + dx) * 4];
                u64 w1 = wrow[(dy * 9 + dx) * 4 + 1];
                #pragma unroll
                for (int px = 0; px < 8; px++) {
                    ffma2(acc[0][px], w0, d[dx + px]);
                    ffma2(acc[1][px], w1, d[dx + px]);
                }
            }
        }
    }

    // scatter-add into destination at gathered global channels (unique per elem)
    float* dstn = dst + (size_t)n * (C_ALL * HW);
    int base_px = y * 32 + x0;
    #pragma unroll
    for (int p = 0; p < 2; p++) {
        int och = o0 + cg * 4 + p * 2;
        float* d0 = dstn + (size_t)ids[och]     * HW + base_px;
        float* d1 = dstn + (size_t)ids[och + 1] * HW + base_px;
        #pragma unroll
        for (int px = 0; px < 8; px++) {
            float lo, hi;
            unpack2(acc[p][px], lo, hi);
            d0[px] += lo;
            d1[px] += hi;
        }
    }
}

// ---------------------------------------------------------------------------
extern "C" void kernel_launch(void* const* d_in, const int* in_sizes, int n_in,
                              void* d_out, int out_size) {
    const float* x    = (const float*)d_in[0];
    const float* arch = (const float*)d_in[1];
    const float* norms= (const float*)d_in[2];
    const int*   idx  = (const int*)  d_in[3];
    const float* w3   = (const float*)d_in[4];
    const float* w5   = (const float*)d_in[5];
    const float* w7   = (const float*)d_in[6];
    const float* w1   = (const float*)d_in[7];
    const float* s3dw = (const float*)d_in[8];
    const float* s3pw = (const float*)d_in[9];
    const float* s5dw = (const float*)d_in[10];
    const float* s5pw = (const float*)d_in[11];
    const float* d3   = (const float*)d_in[12];
    const float* d5   = (const float*)d_in[13];
    float* out = (float*)d_out;

    softmax_kernel<<<1, 32>>>(arch, norms);
    build_w9_kernel<<<dim3(EDGES, 64), 64>>>(w3, w5, w7, w1,
                                             s3dw, s3pw, s5dw, s5pw, d3, d5);

    const int tri[4] = {0, 1, 3, 6};
    for (int node = 0; node < 4; node++) {
        pool_kernel<<<dim3(256, 64), 256>>>(x, out, node);
        for (int i = 0; i <= node; i++) {
            int e = tri[node] + i;
            conv9_kernel<<<dim3(64, 8), 256>>>(x, out, i, node + 1, idx + 64 * e, e);
        }
    }
}

// round 6
// speedup vs baseline: 1.1280x; 1.1280x over previous
#include <cuda_runtime.h>

typedef unsigned long long u64;
typedef unsigned int u32;

#define N_BATCH 64
#define C_ALL 256
#define HW 1024
#define EDGES 10
#define STATE_ELEMS (N_BATCH * C_ALL * HW)   // 16,777,216 floats = 64 MB
#define EOUT_ELEMS (N_BATCH * 64 * HW)       // 4,194,304 floats per edge-half

// Scratch: states 1..3 (state 0 = input x, state 4 = d_out)
__device__ float g_state[3][STATE_ELEMS];
// Per-(half, local-edge) conv outputs: [half][le][n][o][pix]
__device__ float g_eout[2][4][EOUT_ELEMS];
// Combined 9x9 weights, layout [e][ci][tap(81)][o(64)], 16B-aligned for float4
__device__ __align__(16) float g_W9[EDGES * 64 * 81 * 64];
__device__ float g_wsoft[EDGES][12];
// Inverse channel map: g_inv[e][c] = o s.t. idx[e][o]==c, else -1
__device__ int g_inv[EDGES][C_ALL];

__device__ __forceinline__ void ffma2(u64 &d, u64 a, u64 b) {
    asm("fma.rn.f32x2 %0, %1, %2, %0;" : "+l"(d) : "l"(a), "l"(b));
}
__device__ __forceinline__ u64 dup2(float v) {
    u64 d; u32 r = __float_as_uint(v);
    asm("mov.b64 %0, {%1, %1};" : "=l"(d) : "r"(r));
    return d;
}
__device__ __forceinline__ u64 pack2(float a, float b) {
    u64 d; u32 ra = __float_as_uint(a), rb = __float_as_uint(b);
    asm("mov.b64 %0, {%1, %2};" : "=l"(d) : "r"(ra), "r"(rb));
    return d;
}
__device__ __forceinline__ void unpack2(u64 d, float &a, float &b) {
    u32 ra, rb;
    asm("mov.b64 {%0, %1}, %2;" : "=r"(ra), "=r"(rb) : "l"(d));
    a = __uint_as_float(ra); b = __uint_as_float(rb);
}

// ---------------------------------------------------------------------------
// 1) Per-edge softmax of arch params
// ---------------------------------------------------------------------------
__global__ void softmax_kernel(const float* __restrict__ arch,
                               const float* __restrict__ norms) {
    int e = threadIdx.x;
    if (e >= EDGES) return;
    int node = 0, base = 0;
    while (base + node + 1 <= e) { base += node + 1; node++; }
    int i = e - base;
    const float* a = arch + (node * 5 + i) * 12;
    float norm = fmaxf(norms[node * 5 + i], 1e-5f);
    float inv = 1.0f / norm;   // STRENGTH = 1.0
    float t[12];
    float m = -3.4e38f;
    for (int j = 0; j < 12; j++) { t[j] = a[j] * inv; m = fmaxf(m, t[j]); }
    float s = 0.f;
    for (int j = 0; j < 12; j++) { t[j] = expf(t[j] - m); s += t[j]; }
    float invs = 1.0f / s;
    for (int j = 0; j < 12; j++) g_wsoft[e][j] = t[j] * invs;
}

// ---------------------------------------------------------------------------
// 1b) Inverse channel map
// ---------------------------------------------------------------------------
__global__ void inv_kernel(const int* __restrict__ idx) {
    int e = blockIdx.x, c = threadIdx.x;
    int found = -1;
    for (int o = 0; o < 64; o++)
        if (idx[e * 64 + o] == c) found = o;
    g_inv[e][c] = found;
}

// ---------------------------------------------------------------------------
// 2) Fold all 8 conv ops (+identity) of an edge into one 9x9 dense kernel.
// ---------------------------------------------------------------------------
__global__ void build_w9_kernel(
    const float* __restrict__ w3, const float* __restrict__ w5,
    const float* __restrict__ w7, const float* __restrict__ w1,
    const float* __restrict__ s3dw, const float* __restrict__ s3pw,
    const float* __restrict__ s5dw, const float* __restrict__ s5pw,
    const float* __restrict__ d3, const float* __restrict__ d5)
{
    int e = blockIdx.x, ci = blockIdx.y, o = threadIdx.x;
    float wid = g_wsoft[e][0];
    float a3  = g_wsoft[e][1];
    float a5  = g_wsoft[e][2];
    float a7  = g_wsoft[e][3];
    float a1  = g_wsoft[e][4];
    float as3 = g_wsoft[e][7];
    float as5 = g_wsoft[e][8];
    float ad3 = g_wsoft[e][9];
    float ad5 = g_wsoft[e][10];

    int eoc = (e * 64 + o) * 64 + ci;   // OIHW-style [e][o][ci]
    int eci = e * 64 + ci;              // depthwise  [e][ci]
    float pw3 = s3pw[eoc];
    float pw5 = s5pw[eoc];
    float w1v = w1[eoc];

    float* outp = g_W9 + ((e * 64 + ci) * 81) * 64 + o;

    for (int tap = 0; tap < 81; tap++) {
        int dy = tap / 9, dx = tap % 9;
        float v = 0.f;
        if (dy >= 3 && dy <= 5 && dx >= 3 && dx <= 5) {
            int k = (dy - 3) * 3 + (dx - 3);
            v += a3  * w3[eoc * 9 + k];
            v += as3 * pw3 * s3dw[eci * 9 + k];
        }
        if (dy >= 2 && dy <= 6 && dx >= 2 && dx <= 6) {
            int k = (dy - 2) * 5 + (dx - 2);
            v += a5  * w5[eoc * 25 + k];
            v += as5 * pw5 * s5dw[eci * 25 + k];
            if (!((dy - 2) & 1) && !((dx - 2) & 1))
                v += ad3 * d3[eoc * 9 + ((dy - 2) >> 1) * 3 + ((dx - 2) >> 1)];
        }
        if (dy >= 1 && dy <= 7 && dx >= 1 && dx <= 7)
            v += a7 * w7[eoc * 49 + (dy - 1) * 7 + (dx - 1)];
        if (!(dy & 1) && !(dx & 1))
            v += ad5 * d5[eoc * 25 + (dy >> 1) * 5 + (dx >> 1)];
        if (dy == 4 && dx == 4) {
            v += a1 * w1v;
            if (o == ci) v += wid;
        }
        outp[tap * 64] = v;
    }
}

// ---------------------------------------------------------------------------
// 3) Fused 9x9 conv for ALL edges of one node, split-K over ci halves.
//    blockIdx = (n, o-group, le*2+half). Each block: 8 output channels,
//    full 32x32, 32 input channels. Writes private scratch (no races).
// ---------------------------------------------------------------------------
#define PLANE_STRIDE 44
#define PLANE_FLOATS (40 * PLANE_STRIDE)

__global__ void __launch_bounds__(256, 3) conv9_kernel(
    const float* __restrict__ x, const int* __restrict__ idx, int tri_base)
{
    __shared__ float plane[PLANE_FLOATS];   // 40 rows x 44 stride
    __shared__ u64 wsm[81 * 4];             // [tap][4 o-pairs]
    __shared__ int ids[64];

    int le = blockIdx.z >> 1;
    int half = blockIdx.z & 1;
    int e = tri_base + le;

    const float* src = (le == 0) ? x : g_state[le - 1];
    const float* W = g_W9 + (size_t)e * (64 * 81 * 64);

    int tid = threadIdx.x;
    int n = blockIdx.x;
    int o0 = blockIdx.y * 8;

    if (tid < 64) ids[tid] = idx[e * 64 + tid];
    for (int t = tid; t < PLANE_FLOATS; t += 256) plane[t] = 0.f;
    __syncthreads();

    int cg = tid >> 7;          // 0 -> o-pairs 0,1 ; 1 -> o-pairs 2,3
    int r  = tid & 127;
    int y  = r >> 2;            // 0..31 output row
    int x0 = (r & 3) * 8;       // output cols x0..x0+7

    u64 acc[2][8];
    #pragma unroll
    for (int p = 0; p < 2; p++)
        #pragma unroll
        for (int px = 0; px < 8; px++) acc[p][px] = 0ull;

    const float* srcn = src + (size_t)n * (C_ALL * HW);
    int ci_beg = half * 32;

    for (int cc = 0; cc < 32; cc++) {
        int ci = ci_beg + cc;
        __syncthreads();
        const float* pg = srcn + (size_t)ids[ci] * HW;
        #pragma unroll
        for (int k = 0; k < 4; k++) {
            int t = tid + 256 * k;
            plane[(4 + (t >> 5)) * PLANE_STRIDE + 4 + (t & 31)] = pg[t];
        }
        const float* Wci = W + (ci * 81) * 64 + o0;
        if (tid < 162) {
            int tap = tid >> 1, h = tid & 1;
            float4 w4 = *reinterpret_cast<const float4*>(Wci + tap * 64 + h * 4);
            wsm[tap * 4 + h * 2]     = pack2(w4.x, w4.y);
            wsm[tap * 4 + h * 2 + 1] = pack2(w4.z, w4.w);
        }
        __syncthreads();

        const u64* wrow = wsm + cg * 2;
        for (int dy = 0; dy < 9; dy++) {
            const float* rp = plane + (y + dy) * PLANE_STRIDE + x0;
            float4 f0 = *reinterpret_cast<const float4*>(rp);
            float4 f1 = *reinterpret_cast<const float4*>(rp + 4);
            float4 f2 = *reinterpret_cast<const float4*>(rp + 8);
            float4 f3 = *reinterpret_cast<const float4*>(rp + 12);
            u64 d[16];
            d[0]  = dup2(f0.x); d[1]  = dup2(f0.y); d[2]  = dup2(f0.z); d[3]  = dup2(f0.w);
            d[4]  = dup2(f1.x); d[5]  = dup2(f1.y); d[6]  = dup2(f1.z); d[7]  = dup2(f1.w);
            d[8]  = dup2(f2.x); d[9]  = dup2(f2.y); d[10] = dup2(f2.z); d[11] = dup2(f2.w);
            d[12] = dup2(f3.x); d[13] = dup2(f3.y); d[14] = dup2(f3.z); d[15] = dup2(f3.w);
            #pragma unroll
            for (int dx = 0; dx < 9; dx++) {
                u64 w0 = wrow[(dy * 9 + dx) * 4];
                u64 w1 = wrow[(dy * 9 + dx) * 4 + 1];
                #pragma unroll
                for (int px = 0; px < 8; px++) {
                    ffma2(acc[0][px], w0, d[dx + px]);
                    ffma2(acc[1][px], w1, d[dx + px]);
                }
            }
        }
    }

    // write to private scratch: [half][le][n][o][pix]
    float* eo = g_eout[half][le] + (size_t)n * (64 * HW);
    int base_px = y * 32 + x0;
    #pragma unroll
    for (int p = 0; p < 2; p++) {
        int och = o0 + cg * 4 + p * 2;
        float* d0 = eo + (size_t)och       * HW + base_px;
        float* d1 = eo + (size_t)(och + 1) * HW + base_px;
        #pragma unroll
        for (int px = 0; px < 8; px++) {
            float lo, hi;
            unpack2(acc[p][px], lo, hi);
            d0[px] = lo;
            d1[px] = hi;
        }
    }
}

// ---------------------------------------------------------------------------
// 4) Per-node combine: pools (max/avg over incoming states) + gather of
//    edge conv outputs through the inverse channel map. Deterministic order.
// ---------------------------------------------------------------------------
__global__ void __launch_bounds__(256) combine_kernel(
    const float* __restrict__ x, float* __restrict__ out, int node, int tri_base)
{
    __shared__ float pl[1024];
    int c = blockIdx.x, n = blockIdx.y, tid = threadIdx.x;
    float acc[4] = {0.f, 0.f, 0.f, 0.f};

    for (int i = 0; i <= node; i++) {
        const float* s = (i == 0) ? x : g_state[i - 1];
        const float* p = s + ((size_t)n * C_ALL + c) * HW;
        __syncthreads();
        for (int t = tid; t < 1024; t += 256) pl[t] = p[t];
        __syncthreads();
        float w5 = g_wsoft[tri_base + i][5];
        float w6 = g_wsoft[tri_base + i][6];
        #pragma unroll
        for (int k = 0; k < 4; k++) {
            int pix = tid + 256 * k;
            int y = pix >> 5, xx = pix & 31;
            float m = -3.4e38f, sum = 0.f;
            #pragma unroll
            for (int dy = -1; dy <= 1; dy++) {
                int yy = y + dy;
                if (yy < 0 || yy > 31) continue;
                #pragma unroll
                for (int dx = -1; dx <= 1; dx++) {
                    int xc = xx + dx;
                    if (xc < 0 || xc > 31) continue;
                    float v = pl[yy * 32 + xc];
                    m = fmaxf(m, v);
                    sum += v;
                }
            }
            acc[k] += w5 * m + w6 * (sum * (1.f / 9.f));
        }
    }

    for (int le = 0; le <= node; le++) {
        int oc = g_inv[tri_base + le][c];
        if (oc >= 0) {
            const float* e0 = g_eout[0][le] + ((size_t)n * 64 + oc) * HW;
            const float* e1 = g_eout[1][le] + ((size_t)n * 64 + oc) * HW;
            #pragma unroll
            for (int k = 0; k < 4; k++) {
                int pix = tid + 256 * k;
                acc[k] += e0[pix] + e1[pix];
            }
        }
    }

    float* dst = (node == 3) ? out : g_state[node];
    float* dp = dst + ((size_t)n * C_ALL + c) * HW;
    #pragma unroll
    for (int k = 0; k < 4; k++) dp[tid + 256 * k] = acc[k];
}

// ---------------------------------------------------------------------------
extern "C" void kernel_launch(void* const* d_in, const int* in_sizes, int n_in,
                              void* d_out, int out_size) {
    const float* x    = (const float*)d_in[0];
    const float* arch = (const float*)d_in[1];
    const float* norms= (const float*)d_in[2];
    const int*   idx  = (const int*)  d_in[3];
    const float* w3   = (const float*)d_in[4];
    const float* w5   = (const float*)d_in[5];
    const float* w7   = (const float*)d_in[6];
    const float* w1   = (const float*)d_in[7];
    const float* s3dw = (const float*)d_in[8];
    const float* s3pw = (const float*)d_in[9];
    const float* s5dw = (const float*)d_in[10];
    const float* s5pw = (const float*)d_in[11];
    const float* d3   = (const float*)d_in[12];
    const float* d5   = (const float*)d_in[13];
    float* out = (float*)d_out;

    softmax_kernel<<<1, 32>>>(arch, norms);
    inv_kernel<<<EDGES, 256>>>(idx);
    build_w9_kernel<<<dim3(EDGES, 64), 64>>>(w3, w5, w7, w1,
                                             s3dw, s3pw, s5dw, s5pw, d3, d5);

    const int tri[4] = {0, 1, 3, 6};
    for (int node = 0; node < 4; node++) {
        conv9_kernel<<<dim3(64, 8, (node + 1) * 2), 256>>>(x, idx, tri[node]);
        combine_kernel<<<dim3(256, 64), 256>>>(x, out, node, tri[node]);
    }
}

// round 7
// speedup vs baseline: 1.1282x; 1.0002x over previous
#include <cuda_runtime.h>

typedef unsigned long long u64;
typedef unsigned int u32;

#define N_BATCH 64
#define C_ALL 256
#define HW 1024
#define EDGES 10
#define STATE_ELEMS (N_BATCH * C_ALL * HW)   // 16,777,216 floats = 64 MB
#define EOUT_ELEMS (N_BATCH * 64 * HW)       // 4,194,304 floats per edge-half

// Scratch: states 1..3 (state 0 = input x, state 4 = d_out)
__device__ float g_state[3][STATE_ELEMS];
// Per-(half, local-edge) conv outputs: [half][le][n][o][pix]
__device__ float g_eout[2][4][EOUT_ELEMS];
// Combined 9x9 weights, layout [e][ci][tap(81)][o(64)], 16B-aligned for float4
__device__ __align__(16) float g_W9[EDGES * 64 * 81 * 64];
__device__ float g_wsoft[EDGES][12];
// Inverse channel map: g_inv[e][c] = o s.t. idx[e][o]==c, else -1
__device__ int g_inv[EDGES][C_ALL];

__device__ __forceinline__ void ffma2(u64 &d, u64 a, u64 b) {
    asm("fma.rn.f32x2 %0, %1, %2, %0;" : "+l"(d) : "l"(a), "l"(b));
}
__device__ __forceinline__ u64 dup2(float v) {
    u64 d; u32 r = __float_as_uint(v);
    asm("mov.b64 %0, {%1, %1};" : "=l"(d) : "r"(r));
    return d;
}
__device__ __forceinline__ u64 pack2(float a, float b) {
    u64 d; u32 ra = __float_as_uint(a), rb = __float_as_uint(b);
    asm("mov.b64 %0, {%1, %2};" : "=l"(d) : "r"(ra), "r"(rb));
    return d;
}
__device__ __forceinline__ void unpack2(u64 d, float &a, float &b) {
    u32 ra, rb;
    asm("mov.b64 {%0, %1}, %2;" : "=r"(ra), "=r"(rb) : "l"(d));
    a = __uint_as_float(ra); b = __uint_as_float(rb);
}

// ---------------------------------------------------------------------------
// 1) Per-edge softmax of arch params
// ---------------------------------------------------------------------------
__global__ void softmax_kernel(const float* __restrict__ arch,
                               const float* __restrict__ norms) {
    int e = threadIdx.x;
    if (e >= EDGES) return;
    int node = 0, base = 0;
    while (base + node + 1 <= e) { base += node + 1; node++; }
    int i = e - base;
    const float* a = arch + (node * 5 + i) * 12;
    float norm = fmaxf(norms[node * 5 + i], 1e-5f);
    float inv = 1.0f / norm;   // STRENGTH = 1.0
    float t[12];
    float m = -3.4e38f;
    for (int j = 0; j < 12; j++) { t[j] = a[j] * inv; m = fmaxf(m, t[j]); }
    float s = 0.f;
    for (int j = 0; j < 12; j++) { t[j] = expf(t[j] - m); s += t[j]; }
    float invs = 1.0f / s;
    for (int j = 0; j < 12; j++) g_wsoft[e][j] = t[j] * invs;
}

// ---------------------------------------------------------------------------
// 1b) Inverse channel map
// ---------------------------------------------------------------------------
__global__ void inv_kernel(const int* __restrict__ idx) {
    int e = blockIdx.x, c = threadIdx.x;
    int found = -1;
    for (int o = 0; o < 64; o++)
        if (idx[e * 64 + o] == c) found = o;
    g_inv[e][c] = found;
}

// ---------------------------------------------------------------------------
// 2) Fold all 8 conv ops (+identity) of an edge into one 9x9 dense kernel.
// ---------------------------------------------------------------------------
__global__ void build_w9_kernel(
    const float* __restrict__ w3, const float* __restrict__ w5,
    const float* __restrict__ w7, const float* __restrict__ w1,
    const float* __restrict__ s3dw, const float* __restrict__ s3pw,
    const float* __restrict__ s5dw, const float* __restrict__ s5pw,
    const float* __restrict__ d3, const float* __restrict__ d5)
{
    int e = blockIdx.x, ci = blockIdx.y, o = threadIdx.x;
    float wid = g_wsoft[e][0];
    float a3  = g_wsoft[e][1];
    float a5  = g_wsoft[e][2];
    float a7  = g_wsoft[e][3];
    float a1  = g_wsoft[e][4];
    float as3 = g_wsoft[e][7];
    float as5 = g_wsoft[e][8];
    float ad3 = g_wsoft[e][9];
    float ad5 = g_wsoft[e][10];

    int eoc = (e * 64 + o) * 64 + ci;   // OIHW-style [e][o][ci]
    int eci = e * 64 + ci;              // depthwise  [e][ci]
    float pw3 = s3pw[eoc];
    float pw5 = s5pw[eoc];
    float w1v = w1[eoc];

    float* outp = g_W9 + ((e * 64 + ci) * 81) * 64 + o;

    for (int tap = 0; tap < 81; tap++) {
        int dy = tap / 9, dx = tap % 9;
        float v = 0.f;
        if (dy >= 3 && dy <= 5 && dx >= 3 && dx <= 5) {
            int k = (dy - 3) * 3 + (dx - 3);
            v += a3  * w3[eoc * 9 + k];
            v += as3 * pw3 * s3dw[eci * 9 + k];
        }
        if (dy >= 2 && dy <= 6 && dx >= 2 && dx <= 6) {
            int k = (dy - 2) * 5 + (dx - 2);
            v += a5  * w5[eoc * 25 + k];
            v += as5 * pw5 * s5dw[eci * 25 + k];
            if (!((dy - 2) & 1) && !((dx - 2) & 1))
                v += ad3 * d3[eoc * 9 + ((dy - 2) >> 1) * 3 + ((dx - 2) >> 1)];
        }
        if (dy >= 1 && dy <= 7 && dx >= 1 && dx <= 7)
            v += a7 * w7[eoc * 49 + (dy - 1) * 7 + (dx - 1)];
        if (!(dy & 1) && !(dx & 1))
            v += ad5 * d5[eoc * 25 + (dy >> 1) * 5 + (dx >> 1)];
        if (dy == 4 && dx == 4) {
            v += a1 * w1v;
            if (o == ci) v += wid;
        }
        outp[tap * 64] = v;
    }
}

// ---------------------------------------------------------------------------
// 3) Fused 9x9 conv for ALL edges of one node, split-K over ci halves.
//    blockIdx = (n, o-group, le*2+half). Each block: 8 output channels,
//    full 32x32, 32 input channels. Writes private scratch (no races).
// ---------------------------------------------------------------------------
#define PLANE_STRIDE 44
#define PLANE_FLOATS (40 * PLANE_STRIDE)

__global__ void __launch_bounds__(256, 3) conv9_kernel(
    const float* __restrict__ x, const int* __restrict__ idx, int tri_base)
{
    __shared__ float plane[PLANE_FLOATS];   // 40 rows x 44 stride
    __shared__ u64 wsm[81 * 4];             // [tap][4 o-pairs]
    __shared__ int ids[64];

    int le = blockIdx.z >> 1;
    int half = blockIdx.z & 1;
    int e = tri_base + le;

    const float* src = (le == 0) ? x : g_state[le - 1];
    const float* W = g_W9 + (size_t)e * (64 * 81 * 64);

    int tid = threadIdx.x;
    int n = blockIdx.x;
    int o0 = blockIdx.y * 8;

    if (tid < 64) ids[tid] = idx[e * 64 + tid];
    for (int t = tid; t < PLANE_FLOATS; t += 256) plane[t] = 0.f;
    __syncthreads();

    int cg = tid >> 7;          // 0 -> o-pairs 0,1 ; 1 -> o-pairs 2,3
    int r  = tid & 127;
    int y  = r >> 2;            // 0..31 output row
    int x0 = (r & 3) * 8;       // output cols x0..x0+7

    u64 acc[2][8];
    #pragma unroll
    for (int p = 0; p < 2; p++)
        #pragma unroll
        for (int px = 0; px < 8; px++) acc[p][px] = 0ull;

    const float* srcn = src + (size_t)n * (C_ALL * HW);
    int ci_beg = half * 32;

    for (int cc = 0; cc < 32; cc++) {
        int ci = ci_beg + cc;
        __syncthreads();
        const float* pg = srcn + (size_t)ids[ci] * HW;
        #pragma unroll
        for (int k = 0; k < 4; k++) {
            int t = tid + 256 * k;
            plane[(4 + (t >> 5)) * PLANE_STRIDE + 4 + (t & 31)] = pg[t];
        }
        const float* Wci = W + (ci * 81) * 64 + o0;
        if (tid < 162) {
            int tap = tid >> 1, h = tid & 1;
            float4 w4 = *reinterpret_cast<const float4*>(Wci + tap * 64 + h * 4);
            wsm[tap * 4 + h * 2]     = pack2(w4.x, w4.y);
            wsm[tap * 4 + h * 2 + 1] = pack2(w4.z, w4.w);
        }
        __syncthreads();

        const u64* wrow = wsm + cg * 2;
        for (int dy = 0; dy < 9; dy++) {
            const float* rp = plane + (y + dy) * PLANE_STRIDE + x0;
            float4 f0 = *reinterpret_cast<const float4*>(rp);
            float4 f1 = *reinterpret_cast<const float4*>(rp + 4);
            float4 f2 = *reinterpret_cast<const float4*>(rp + 8);
            float4 f3 = *reinterpret_cast<const float4*>(rp + 12);
            u64 d[16];
            d[0]  = dup2(f0.x); d[1]  = dup2(f0.y); d[2]  = dup2(f0.z); d[3]  = dup2(f0.w);
            d[4]  = dup2(f1.x); d[5]  = dup2(f1.y); d[6]  = dup2(f1.z); d[7]  = dup2(f1.w);
            d[8]  = dup2(f2.x); d[9]  = dup2(f2.y); d[10] = dup2(f2.z); d[11] = dup2(f2.w);
            d[12] = dup2(f3.x); d[13] = dup2(f3.y); d[14] = dup2(f3.z); d[15] = dup2(f3.w);
            #pragma unroll
            for (int dx = 0; dx < 9; dx++) {
                u64 w0 = wrow[(dy * 9 + dx) * 4];
                u64 w1 = wrow[(dy * 9 + dx) * 4 + 1];
                #pragma unroll
                for (int px = 0; px < 8; px++) {
                    ffma2(acc[0][px], w0, d[dx + px]);
                    ffma2(acc[1][px], w1, d[dx + px]);
                }
            }
        }
    }

    // write to private scratch: [half][le][n][o][pix]
    float* eo = g_eout[half][le] + (size_t)n * (64 * HW);
    int base_px = y * 32 + x0;
    #pragma unroll
    for (int p = 0; p < 2; p++) {
        int och = o0 + cg * 4 + p * 2;
        float* d0 = eo + (size_t)och       * HW + base_px;
        float* d1 = eo + (size_t)(och + 1) * HW + base_px;
        #pragma unroll
        for (int px = 0; px < 8; px++) {
            float lo, hi;
            unpack2(acc[p][px], lo, hi);
            d0[px] = lo;
            d1[px] = hi;
        }
    }
}

// ---------------------------------------------------------------------------
// 4) Per-node combine: pools (max/avg over incoming states) + gather of
//    edge conv outputs through the inverse channel map. Deterministic order.
// ---------------------------------------------------------------------------
__global__ void __launch_bounds__(256) combine_kernel(
    const float* __restrict__ x, float* __restrict__ out, int node, int tri_base)
{
    __shared__ float pl[1024];
    int c = blockIdx.x, n = blockIdx.y, tid = threadIdx.x;
    float acc[4] = {0.f, 0.f, 0.f, 0.f};

    for (int i = 0; i <= node; i++) {
        const float* s = (i == 0) ? x : g_state[i - 1];
        const float* p = s + ((size_t)n * C_ALL + c) * HW;
        __syncthreads();
        for (int t = tid; t < 1024; t += 256) pl[t] = p[t];
        __syncthreads();
        float w5 = g_wsoft[tri_base + i][5];
        float w6 = g_wsoft[tri_base + i][6];
        #pragma unroll
        for (int k = 0; k < 4; k++) {
            int pix = tid + 256 * k;
            int y = pix >> 5, xx = pix & 31;
            float m = -3.4e38f, sum = 0.f;
            #pragma unroll
            for (int dy = -1; dy <= 1; dy++) {
                int yy = y + dy;
                if (yy < 0 || yy > 31) continue;
                #pragma unroll
                for (int dx = -1; dx <= 1; dx++) {
                    int xc = xx + dx;
                    if (xc < 0 || xc > 31) continue;
                    float v = pl[yy * 32 + xc];
                    m = fmaxf(m, v);
                    sum += v;
                }
            }
            acc[k] += w5 * m + w6 * (sum * (1.f / 9.f));
        }
    }

    for (int le = 0; le <= node; le++) {
        int oc = g_inv[tri_base + le][c];
        if (oc >= 0) {
            const float* e0 = g_eout[0][le] + ((size_t)n * 64 + oc) * HW;
            const float* e1 = g_eout[1][le] + ((size_t)n * 64 + oc) * HW;
            #pragma unroll
            for (int k = 0; k < 4; k++) {
                int pix = tid + 256 * k;
                acc[k] += e0[pix] + e1[pix];
            }
        }
    }

    float* dst = (node == 3) ? out : g_state[node];
    float* dp = dst + ((size_t)n * C_ALL + c) * HW;
    #pragma unroll
    for (int k = 0; k < 4; k++) dp[tid + 256 * k] = acc[k];
}

// ---------------------------------------------------------------------------
extern "C" void kernel_launch(void* const* d_in, const int* in_sizes, int n_in,
                              void* d_out, int out_size) {
    const float* x    = (const float*)d_in[0];
    const float* arch = (const float*)d_in[1];
    const float* norms= (const float*)d_in[2];
    const int*   idx  = (const int*)  d_in[3];
    const float* w3   = (const float*)d_in[4];
    const float* w5   = (const float*)d_in[5];
    const float* w7   = (const float*)d_in[6];
    const float* w1   = (const float*)d_in[7];
    const float* s3dw = (const float*)d_in[8];
    const float* s3pw = (const float*)d_in[9];
    const float* s5dw = (const float*)d_in[10];
    const float* s5pw = (const float*)d_in[11];
    const float* d3   = (const float*)d_in[12];
    const float* d5   = (const float*)d_in[13];
    float* out = (float*)d_out;

    softmax_kernel<<<1, 32>>>(arch, norms);
    inv_kernel<<<EDGES, 256>>>(idx);
    build_w9_kernel<<<dim3(EDGES, 64), 64>>>(w3, w5, w7, w1,
                                             s3dw, s3pw, s5dw, s5pw, d3, d5);

    const int tri[4] = {0, 1, 3, 6};
    for (int node = 0; node < 4; node++) {
        conv9_kernel<<<dim3(64, 8, (node + 1) * 2), 256>>>(x, idx, tri[node]);
        combine_kernel<<<dim3(256, 64), 256>>>(x, out, node, tri[node]);
    }
}